// round 15
// baseline (speedup 1.0000x reference)
#include <cuda_runtime.h>
#include <cstdint>

// MC_Module_Batch: bilinear backward warp + weight + sum over R.
// 2-stage cp.async pipeline, fine 32x8 tiles, 1 px/thread -> ~40 regs ->
// 6 CTAs/SM, 2048 streaming jobs.
// pred [B,R,C,H,W], mv [B,R,2,H,W] (quarter-pel), weight [B,R,1,H,W] -> out [B,C,H,W]

#define Bv 4
#define Rv 2
#define Cv 19
#define Hv 256
#define Wv 512
#define HW (Hv * Wv)

#define TILE_H 8
#define PADY 7
#define PADX 8
#define TROWS (TILE_H + 2 * PADY + 1)  // 23
#define TCOLS 48
#define TC4   (TCOLS / 4)               // 12 float4 per row
#define TSZ   (TROWS * TCOLS)           // 1104 floats
#define TSZ4  (TSZ / 4)                 // 276 float4
#define SMEM_BYTES (2 * 2 * TSZ * 4)    // 17664 B

__device__ __forceinline__ void cp_async16(uint32_t smem, const void* g) {
    asm volatile("cp.async.cg.shared.global [%0], [%1], 16;" :: "r"(smem), "l"(g));
}
__device__ __forceinline__ void cp_commit() {
    asm volatile("cp.async.commit_group;");
}
template<int N> __device__ __forceinline__ void cp_wait() {
    asm volatile("cp.async.wait_group %0;" :: "n"(N));
}

__global__ __launch_bounds__(256, 6)
void mc_warp_kernel(const float* __restrict__ pred,
                    const float* __restrict__ mv,
                    const float* __restrict__ wgt,
                    float* __restrict__ out)
{
    extern __shared__ __align__(16) float smem[];   // [2 stages][2 r][TSZ]
    const uint32_t smem_u32 = (uint32_t)__cvta_generic_to_shared(smem);

    const int tid = threadIdx.x;
    const int tx  = tid & 31;
    const int ty  = tid >> 5;            // 0..7
    const int bx  = blockIdx.x, by = blockIdx.y, b = blockIdx.z;
    const int x0blk = bx * 32;
    const int y0blk = by * TILE_H;
    const int x = x0blk + tx;
    const int y = y0blk + ty;
    const int wbase = min(max(x0blk - PADX, 0), Wv - TCOLS);
    const int rowbase = y0blk - PADY;

    // ---- Precompute taps (1 px/thread, 2 r) ----
    // Fast: tile index of top-left tap (UNCLAMPED coords); taps at
    //   +0, +1, +TCOLS, +TCOLS+1. Row-clamped tile + exactly-zero weights on
    //   invalid taps keep this exact; window-escaping taps -> exact fallback.
    // Fallback (bit30): low17 = clamped global idx, bit20=dx, bit21=dy.
    float w4[2][4];
    int   idesc[2];
    int   fall = 0;
    const int pix = y * Wv + x;
#pragma unroll
    for (int r = 0; r < Rv; ++r) {
        const int nr = b * Rv + r;
        const float mvx = __ldg(mv + (size_t)(nr * 2) * HW + pix) * 0.25f;
        const float mvy = __ldg(mv + (size_t)(nr * 2 + 1) * HW + pix) * 0.25f;
        const float w   = __ldg(wgt + (size_t)nr * HW + pix);

        const float gx = (float)x + mvx;
        const float gy = (float)y + mvy;
        const float x0f = floorf(gx), y0f = floorf(gy);
        const float wx1 = gx - x0f, wx0 = 1.0f - wx1;
        const float wy1 = gy - y0f, wy0 = 1.0f - wy1;

        const int x0 = (int)x0f, y0 = (int)y0f;
        const int x1 = x0 + 1,   y1 = y0 + 1;

        const float vx0 = ((unsigned)x0 < (unsigned)Wv) ? 1.0f : 0.0f;
        const float vx1 = ((unsigned)x1 < (unsigned)Wv) ? 1.0f : 0.0f;
        const float vy0 = ((unsigned)y0 < (unsigned)Hv) ? 1.0f : 0.0f;
        const float vy1 = ((unsigned)y1 < (unsigned)Hv) ? 1.0f : 0.0f;

        w4[r][0] = wy0 * wx0 * vy0 * vx0 * w;
        w4[r][1] = wy0 * wx1 * vy0 * vx1 * w;
        w4[r][2] = wy1 * wx0 * vy1 * vx0 * w;
        w4[r][3] = wy1 * wx1 * vy1 * vx1 * w;

        const int tT = y0 - rowbase;   // UNCLAMPED
        const int tX = x0 - wbase;     // UNCLAMPED
        if ((unsigned)tT <= (TROWS - 2) && (unsigned)tX <= (TCOLS - 2)) {
            idesc[r] = tT * TCOLS + tX;
        } else {
            const int cx0 = min(max(x0, 0), Wv - 1);
            const int cx1 = min(max(x1, 0), Wv - 1);
            const int cy0 = min(max(y0, 0), Hv - 1);
            const int cy1 = min(max(y1, 0), Hv - 1);
            idesc[r] = 0x40000000 | ((cy1 - cy0) << 21)
                     | ((cx1 - cx0) << 20) | (cy0 * Wv + cx0);
            fall = 1;
        }
    }
    const int anyfall = __syncthreads_or(fall);

    const float* pb0 = pred + (size_t)(b * Rv + 0) * Cv * HW;
    const float* pb1 = pred + (size_t)(b * Rv + 1) * Cv * HW;
    const int wb4 = wbase >> 2;

    float* ob = out + (size_t)b * Cv * HW + pix;

    auto load_stage = [&](int c, int st) {
        const float4* s0 = (const float4*)(pb0 + (size_t)c * HW);
        const float4* s1 = (const float4*)(pb1 + (size_t)c * HW);
        const uint32_t d0 = smem_u32 + (uint32_t)(st * 2 * TSZ) * 4u;
        for (int i = tid; i < TSZ4; i += 256) {
            const int row = i / TC4;
            const int c4  = i - row * TC4;
            const int gcy = min(max(rowbase + row, 0), Hv - 1);
            const int gi  = gcy * (Wv / 4) + wb4 + c4;
            cp_async16(d0 + (uint32_t)i * 16u, s0 + gi);
            cp_async16(d0 + (uint32_t)(TSZ * 4) + (uint32_t)i * 16u, s1 + gi);
        }
    };

    load_stage(0, 0);
    cp_commit();

    if (!anyfall) {
        for (int c = 0; c < Cv; ++c) {
            const int st = c & 1;
            if (c + 1 < Cv) { load_stage(c + 1, st ^ 1); cp_commit(); cp_wait<1>(); }
            else            { cp_wait<0>(); }
            __syncthreads();

            const float* tbase = smem + st * 2 * TSZ;
            float s = 0.0f;
#pragma unroll
            for (int r = 0; r < Rv; ++r) {
                const float* tb = tbase + r * TSZ + idesc[r];
                s = fmaf(w4[r][0], tb[0],
                    fmaf(w4[r][1], tb[1],
                    fmaf(w4[r][2], tb[TCOLS],
                    fmaf(w4[r][3], tb[TCOLS + 1], s))));
            }
            ob[(size_t)c * HW] = s;
            __syncthreads();
        }
    } else {
        for (int c = 0; c < Cv; ++c) {
            const int st = c & 1;
            if (c + 1 < Cv) { load_stage(c + 1, st ^ 1); cp_commit(); cp_wait<1>(); }
            else            { cp_wait<0>(); }
            __syncthreads();

            const float* tbase = smem + st * 2 * TSZ;
            float s = 0.0f;
#pragma unroll
            for (int r = 0; r < Rv; ++r) {
                const int d = idesc[r];
                float t0v, t1v, b0v, b1v;
                if (d < 0x40000000) {
                    const float* tb = tbase + r * TSZ + d;
                    t0v = tb[0];      t1v = tb[1];
                    b0v = tb[TCOLS];  b1v = tb[TCOLS + 1];
                } else {
                    const int gT = d & 0x1FFFF;
                    const int dv = (d >> 20) & 1;
                    const int gB = gT + ((d >> 21) & 1) * Wv;
                    const float* pc = (r ? pb1 : pb0) + (size_t)c * HW;
                    t0v = __ldg(pc + gT);  t1v = __ldg(pc + gT + dv);
                    b0v = __ldg(pc + gB);  b1v = __ldg(pc + gB + dv);
                }
                s = fmaf(w4[r][0], t0v,
                    fmaf(w4[r][1], t1v,
                    fmaf(w4[r][2], b0v,
                    fmaf(w4[r][3], b1v, s))));
            }
            ob[(size_t)c * HW] = s;
            __syncthreads();
        }
    }
}

extern "C" void kernel_launch(void* const* d_in, const int* in_sizes, int n_in,
                              void* d_out, int out_size)
{
    const float* pred = (const float*)d_in[0];
    const float* mv   = (const float*)d_in[1];
    const float* wgt  = (const float*)d_in[2];
    float* out        = (float*)d_out;

    cudaFuncSetAttribute(mc_warp_kernel,
                         cudaFuncAttributeMaxDynamicSharedMemorySize, SMEM_BYTES);

    dim3 grid(Wv / 32, Hv / TILE_H, Bv);   // 16 x 32 x 4 = 2048 blocks
    mc_warp_kernel<<<grid, 256, SMEM_BYTES>>>(pred, mv, wgt, out);
}

// round 16
// speedup vs baseline: 1.1351x; 1.1351x over previous
#include <cuda_runtime.h>
#include <cstdint>

// MC_Module_Batch: bilinear backward warp + weight + sum over R.
// 3-stage cp.async ring (1 barrier/iter), 32x8 tiles, 1 px/thread,
// 6 CTAs/SM, shift-only loader indexing.
// pred [B,R,C,H,W], mv [B,R,2,H,W] (quarter-pel), weight [B,R,1,H,W] -> out [B,C,H,W]

#define Bv 4
#define Rv 2
#define Cv 19
#define Hv 256
#define Wv 512
#define HW (Hv * Wv)

#define TILE_H 8
#define PADY 7
#define PADX 16
#define TROWS (TILE_H + 2 * PADY + 1)  // 23
#define TCOLS 64
#define TSZ   (TROWS * TCOLS)           // 1472 floats
#define TSZ4  (TSZ / 4)                 // 368 float4
#define NSTAGE 3
#define SMEM_BYTES (NSTAGE * 2 * TSZ * 4)   // 35328 B

__device__ __forceinline__ void cp_async16(uint32_t smem, const void* g) {
    asm volatile("cp.async.cg.shared.global [%0], [%1], 16;" :: "r"(smem), "l"(g));
}
__device__ __forceinline__ void cp_commit() {
    asm volatile("cp.async.commit_group;");
}
template<int N> __device__ __forceinline__ void cp_wait() {
    asm volatile("cp.async.wait_group %0;" :: "n"(N));
}

__global__ __launch_bounds__(256, 6)
void mc_warp_kernel(const float* __restrict__ pred,
                    const float* __restrict__ mv,
                    const float* __restrict__ wgt,
                    float* __restrict__ out)
{
    extern __shared__ __align__(16) float smem[];   // [NSTAGE][2 r][TSZ]
    const uint32_t smem_u32 = (uint32_t)__cvta_generic_to_shared(smem);

    const int tid = threadIdx.x;
    const int tx  = tid & 31;
    const int ty  = tid >> 5;            // 0..7
    const int bx  = blockIdx.x, by = blockIdx.y, b = blockIdx.z;
    const int x0blk = bx * 32;
    const int y0blk = by * TILE_H;
    const int x = x0blk + tx;
    const int y = y0blk + ty;
    const int wbase = min(max(x0blk - PADX, 0), Wv - TCOLS);
    const int rowbase = y0blk - PADY;

    // ---- Precompute taps (1 px/thread, 2 r) ----
    // Fast: tile index of top-left tap (UNCLAMPED coords); taps at
    //   +0, +1, +TCOLS, +TCOLS+1. Row-clamped tile + exactly-zero weights on
    //   invalid taps keep this exact; window-escaping taps -> exact fallback.
    // Fallback (bit30): low17 = clamped global idx, bit20=dx, bit21=dy.
    float w4[2][4];
    int   idesc[2];
    int   fall = 0;
    const int pix = y * Wv + x;
#pragma unroll
    for (int r = 0; r < Rv; ++r) {
        const int nr = b * Rv + r;
        const float mvx = __ldg(mv + (size_t)(nr * 2) * HW + pix) * 0.25f;
        const float mvy = __ldg(mv + (size_t)(nr * 2 + 1) * HW + pix) * 0.25f;
        const float w   = __ldg(wgt + (size_t)nr * HW + pix);

        const float gx = (float)x + mvx;
        const float gy = (float)y + mvy;
        const float x0f = floorf(gx), y0f = floorf(gy);
        const float wx1 = gx - x0f, wx0 = 1.0f - wx1;
        const float wy1 = gy - y0f, wy0 = 1.0f - wy1;

        const int x0 = (int)x0f, y0 = (int)y0f;
        const int x1 = x0 + 1,   y1 = y0 + 1;

        const float vx0 = ((unsigned)x0 < (unsigned)Wv) ? 1.0f : 0.0f;
        const float vx1 = ((unsigned)x1 < (unsigned)Wv) ? 1.0f : 0.0f;
        const float vy0 = ((unsigned)y0 < (unsigned)Hv) ? 1.0f : 0.0f;
        const float vy1 = ((unsigned)y1 < (unsigned)Hv) ? 1.0f : 0.0f;

        w4[r][0] = wy0 * wx0 * vy0 * vx0 * w;
        w4[r][1] = wy0 * wx1 * vy0 * vx1 * w;
        w4[r][2] = wy1 * wx0 * vy1 * vx0 * w;
        w4[r][3] = wy1 * wx1 * vy1 * vx1 * w;

        const int tT = y0 - rowbase;   // UNCLAMPED
        const int tX = x0 - wbase;     // UNCLAMPED
        if ((unsigned)tT <= (TROWS - 2) && (unsigned)tX <= (TCOLS - 2)) {
            idesc[r] = tT * TCOLS + tX;
        } else {
            const int cx0 = min(max(x0, 0), Wv - 1);
            const int cx1 = min(max(x1, 0), Wv - 1);
            const int cy0 = min(max(y0, 0), Hv - 1);
            const int cy1 = min(max(y1, 0), Hv - 1);
            idesc[r] = 0x40000000 | ((cy1 - cy0) << 21)
                     | ((cx1 - cx0) << 20) | (cy0 * Wv + cx0);
            fall = 1;
        }
    }
    const int anyfall = __syncthreads_or(fall);

    const float* pb0 = pred + (size_t)(b * Rv + 0) * Cv * HW;
    const float* pb1 = pred + (size_t)(b * Rv + 1) * Cv * HW;
    const int wb4 = wbase >> 2;

    float* ob = out + (size_t)b * Cv * HW + pix;

    auto load_stage = [&](int c, int st) {
        const float4* s0 = (const float4*)(pb0 + (size_t)c * HW);
        const float4* s1 = (const float4*)(pb1 + (size_t)c * HW);
        const uint32_t d0 = smem_u32 + (uint32_t)(st * 2 * TSZ) * 4u;
#pragma unroll
        for (int i = tid; i < TSZ4; i += 256) {
            const int row = i >> 4;            // 16 float4 per tile row
            const int c4  = i & 15;
            const int gcy = min(max(rowbase + row, 0), Hv - 1);
            const int gi  = gcy * (Wv / 4) + wb4 + c4;
            cp_async16(d0 + (uint32_t)i * 16u, s0 + gi);
            cp_async16(d0 + (uint32_t)(TSZ * 4) + (uint32_t)i * 16u, s1 + gi);
        }
    };

    // Preload channels 0 and 1 into stages 0 and 1 (separate groups).
    load_stage(0, 0);
    cp_commit();
    load_stage(1, 1);
    cp_commit();

    int st = 0;   // stage holding channel c
    int ld = 2;   // stage for channel c+2

    if (!anyfall) {
        for (int c = 0; c < Cv; ++c) {
            if (c + 1 < Cv) cp_wait<1>();   // stage st's group retired
            else            cp_wait<0>();
            __syncthreads();                // all iter c-1 gathers done; data visible
            if (c + 2 < Cv) { load_stage(c + 2, ld); cp_commit(); }

            const float* tbase = smem + st * 2 * TSZ;
            float s = 0.0f;
#pragma unroll
            for (int r = 0; r < Rv; ++r) {
                const float* tb = tbase + r * TSZ + idesc[r];
                s = fmaf(w4[r][0], tb[0],
                    fmaf(w4[r][1], tb[1],
                    fmaf(w4[r][2], tb[TCOLS],
                    fmaf(w4[r][3], tb[TCOLS + 1], s))));
            }
            ob[(size_t)c * HW] = s;
            st = (st == NSTAGE - 1) ? 0 : st + 1;
            ld = (ld == NSTAGE - 1) ? 0 : ld + 1;
        }
    } else {
        for (int c = 0; c < Cv; ++c) {
            if (c + 1 < Cv) cp_wait<1>();
            else            cp_wait<0>();
            __syncthreads();
            if (c + 2 < Cv) { load_stage(c + 2, ld); cp_commit(); }

            const float* tbase = smem + st * 2 * TSZ;
            float s = 0.0f;
#pragma unroll
            for (int r = 0; r < Rv; ++r) {
                const int d = idesc[r];
                float t0v, t1v, b0v, b1v;
                if (d < 0x40000000) {
                    const float* tb = tbase + r * TSZ + d;
                    t0v = tb[0];      t1v = tb[1];
                    b0v = tb[TCOLS];  b1v = tb[TCOLS + 1];
                } else {
                    const int gT = d & 0x1FFFF;
                    const int dv = (d >> 20) & 1;
                    const int gB = gT + ((d >> 21) & 1) * Wv;
                    const float* pc = (r ? pb1 : pb0) + (size_t)c * HW;
                    t0v = __ldg(pc + gT);  t1v = __ldg(pc + gT + dv);
                    b0v = __ldg(pc + gB);  b1v = __ldg(pc + gB + dv);
                }
                s = fmaf(w4[r][0], t0v,
                    fmaf(w4[r][1], t1v,
                    fmaf(w4[r][2], b0v,
                    fmaf(w4[r][3], b1v, s))));
            }
            ob[(size_t)c * HW] = s;
            st = (st == NSTAGE - 1) ? 0 : st + 1;
            ld = (ld == NSTAGE - 1) ? 0 : ld + 1;
        }
    }
}

extern "C" void kernel_launch(void* const* d_in, const int* in_sizes, int n_in,
                              void* d_out, int out_size)
{
    const float* pred = (const float*)d_in[0];
    const float* mv   = (const float*)d_in[1];
    const float* wgt  = (const float*)d_in[2];
    float* out        = (float*)d_out;

    cudaFuncSetAttribute(mc_warp_kernel,
                         cudaFuncAttributeMaxDynamicSharedMemorySize, SMEM_BYTES);

    dim3 grid(Wv / 32, Hv / TILE_H, Bv);   // 16 x 32 x 4 = 2048 blocks
    mc_warp_kernel<<<grid, 256, SMEM_BYTES>>>(pred, mv, wgt, out);
}